// round 6
// baseline (speedup 1.0000x reference)
#include <cuda_runtime.h>

#define D     2048
#define RNK   8
#define RF    32
#define NROWS 16384
#define EPS   1e-5f

typedef unsigned long long ull;

// ---------------- device scratch (static globals: no allocation) ----------------
__device__ __align__(16) float g_WgInT[RNK * D];    // gamma[d]*W_in[d][k], transposed [k][d]
__device__ __align__(16) float g_WgDownT[RF * D];   // gamma[d]*W_down[d][c], transposed [c][d]
__device__ __align__(16) float g_GS[D];             // gamma*D_skip
__device__ __align__(16) float g_C[D];              // b_out + beta*D_skip
__device__ float g_Gk[RNK], g_Bk[RNK], g_decay[RNK];
__device__ float g_Gd[RF], g_Bd[RF];
__device__ __align__(16) float g_uT[32 * 4096];     // [(b*8+k)][s]
__device__ __align__(16) float g_hT[32 * 4096];     // [(b*8+k)][s]
__device__ float g_mu[NROWS], g_rstd[NROWS];

// ---------------- helpers ----------------
__device__ __forceinline__ ull pack2(float lo, float hi) {
    ull r; asm("mov.b64 %0,{%1,%2};" : "=l"(r) : "f"(lo), "f"(hi)); return r;
}
__device__ __forceinline__ void unpack2(ull v, float &lo, float &hi) {
    asm("mov.b64 {%0,%1},%2;" : "=f"(lo), "=f"(hi) : "l"(v));
}
__device__ __forceinline__ void fma2(ull &acc, ull a, ull b) {
    asm("fma.rn.f32x2 %0,%1,%2,%0;" : "+l"(acc) : "l"(a), "l"(b));
}
__device__ __forceinline__ ull add2(ull a, ull b) {
    ull r; asm("add.rn.f32x2 %0,%1,%2;" : "=l"(r) : "l"(a), "l"(b)); return r;
}
__device__ __forceinline__ float wred(float v) {
    v += __shfl_xor_sync(0xffffffffu, v, 16);
    v += __shfl_xor_sync(0xffffffffu, v, 8);
    v += __shfl_xor_sync(0xffffffffu, v, 4);
    v += __shfl_xor_sync(0xffffffffu, v, 2);
    v += __shfl_xor_sync(0xffffffffu, v, 1);
    return v;
}
__device__ __forceinline__ float f4get(const float4 &v, int e) {
    return e == 0 ? v.x : e == 1 ? v.y : e == 2 ? v.z : v.w;
}

// ================= k0a: elementwise precompute (transposed scaled weights) =================
__global__ void k0a_kernel(const float* __restrict__ gamma, const float* __restrict__ beta,
                           const float* __restrict__ W_in, const float* __restrict__ W_down,
                           const float* __restrict__ D_skip, const float* __restrict__ b_out) {
    int i = blockIdx.x * blockDim.x + threadIdx.x;   // 65536 threads
    if (i < RF * D) {
        int d = i >> 5, c = i & 31;
        g_WgDownT[c * D + d] = gamma[d] * W_down[i];
    }
    if (i < RNK * D) {
        int d = i >> 3, k = i & 7;
        g_WgInT[k * D + d] = gamma[d] * W_in[i];
    }
    if (i < D) {
        g_GS[i] = gamma[i] * D_skip[i];
        g_C[i]  = b_out[i] + beta[i] * D_skip[i];
    }
}

// ================= k0b: folded-LN reduction constants + decay =================
__global__ void k0b_kernel(const float* __restrict__ gamma, const float* __restrict__ beta,
                           const float* __restrict__ W_in, const float* __restrict__ b_in,
                           const float* __restrict__ dlogit,
                           const float* __restrict__ W_down, const float* __restrict__ b_down) {
    int q = (blockIdx.x * blockDim.x + threadIdx.x) >> 5;
    int lane = threadIdx.x & 31;
    if (q < 8) {
        float a = 0.f;
        for (int d = lane; d < D; d += 32) a += gamma[d] * W_in[d * RNK + q];
        a = wred(a); if (!lane) g_Gk[q] = a;
    } else if (q < 16) {
        int k = q - 8; float a = 0.f;
        for (int d = lane; d < D; d += 32) a += beta[d] * W_in[d * RNK + k];
        a = wred(a); if (!lane) g_Bk[k] = a + b_in[k];
    } else if (q < 48) {
        int c = q - 16; float a = 0.f;
        for (int d = lane; d < D; d += 32) a += gamma[d] * W_down[d * RF + c];
        a = wred(a); if (!lane) g_Gd[c] = a;
    } else if (q < 80) {
        int c = q - 48; float a = 0.f;
        for (int d = lane; d < D; d += 32) a += beta[d] * W_down[d * RF + c];
        a = wred(a); if (!lane) g_Bd[c] = a + b_down[c];
    } else if (q == 80 && lane < RNK) {
        g_decay[lane] = 1.f / (1.f + expf(-dlogit[lane]));
    }
}

// ================= k1: single pass over x -> per-row (mu, rstd) and u (folded LN) ==========
// 16 rows/block, 512 threads. Warp w owns d-chunk [128w,128w+128), lane owns 4 d's.
__global__ void __launch_bounds__(512) k1_kernel(const float* __restrict__ x) {
    __shared__ float udot_s[16 * 8];
    __shared__ float st_s[32];
    __shared__ float musA[16], rstdsA[16];
    int tid = threadIdx.x, w = tid >> 5, lane = tid & 31;
    int rowBase = blockIdx.x * 16;

    if (tid < 128) udot_s[tid] = 0.f;
    if (tid < 32)  st_s[tid] = 0.f;
    __syncthreads();

    int d0 = w * 128 + lane * 4;
    float4 wk[8];
#pragma unroll
    for (int k = 0; k < 8; k++) wk[k] = *(const float4*)(g_WgInT + k * D + d0);
    ull w2[4][4];  // [element e][k-pair p]
#pragma unroll
    for (int e = 0; e < 4; e++)
#pragma unroll
        for (int p = 0; p < 4; p++)
            w2[e][p] = pack2(f4get(wk[2 * p], e), f4get(wk[2 * p + 1], e));

#pragma unroll
    for (int r = 0; r < 16; r++) {
        const float4 xv = *(const float4*)(x + (size_t)(rowBase + r) * D + d0);
        float s1 = xv.x + xv.y + xv.z + xv.w;
        float s2 = xv.x * xv.x + xv.y * xv.y + xv.z * xv.z + xv.w * xv.w;
        ull acc[4]; acc[0] = 0; acc[1] = 0; acc[2] = 0; acc[3] = 0;
        float xe[4] = {xv.x, xv.y, xv.z, xv.w};
#pragma unroll
        for (int e = 0; e < 4; e++) {
            ull x2 = pack2(xe[e], xe[e]);
#pragma unroll
            for (int p = 0; p < 4; p++) fma2(acc[p], w2[e][p], x2);
        }
        ull ss = pack2(s1, s2);
#pragma unroll
        for (int m = 16; m >= 1; m >>= 1) {
            ss = add2(ss, __shfl_xor_sync(0xffffffffu, ss, m));
#pragma unroll
            for (int p = 0; p < 4; p++)
                acc[p] = add2(acc[p], __shfl_xor_sync(0xffffffffu, acc[p], m));
        }
        if (lane == 0) {
            float a, b; unpack2(ss, a, b);
            atomicAdd(&st_s[2 * r], a); atomicAdd(&st_s[2 * r + 1], b);
#pragma unroll
            for (int p = 0; p < 4; p++) {
                float u0, u1; unpack2(acc[p], u0, u1);
                atomicAdd(&udot_s[r * 8 + 2 * p], u0);
                atomicAdd(&udot_s[r * 8 + 2 * p + 1], u1);
            }
        }
    }
    __syncthreads();
    if (tid < 16) {
        float s1 = st_s[2 * tid], s2 = st_s[2 * tid + 1];
        float mu = s1 * (1.f / D);
        float var = s2 * (1.f / D) - mu * mu;
        float rs = rsqrtf(var + EPS);
        musA[tid] = mu; rstdsA[tid] = rs;
        g_mu[rowBase + tid] = mu; g_rstd[rowBase + tid] = rs;
    }
    __syncthreads();
    if (tid < 128) {
        int r = tid >> 3, k = tid & 7, row = rowBase + r;
        float u = rstdsA[r] * (udot_s[tid] - musA[r] * g_Gk[k]) + g_Bk[k];
        g_uT[(((row >> 12) * 8) + k) * 4096 + (row & 4095)] = u;
    }
}

// ================= k2: 32 independent first-order scans, len 4096 =================
__global__ void k2_kernel() {
    int blk = blockIdx.x;                 // 0..31 = b*8+k
    const float a = g_decay[blk & 7];
    const float* u = g_uT + blk * 4096;
    float* h = g_hT + blk * 4096;
    int t = threadIdx.x;                  // 256 threads, chunk = 16
    float a2 = a * a, a4 = a2 * a2, a8 = a4 * a4, a16 = a8 * a8;

    __shared__ float he[256];
    __shared__ float carry[256];

    int base = t * 16;
    float loc = 0.f;
#pragma unroll
    for (int i = 0; i < 16; i++) loc = a * loc + u[base + i];
    he[t] = loc;
    __syncthreads();
    if (t == 0) {
        float c = 0.f; carry[0] = 0.f;
        for (int j = 1; j < 256; j++) { c = he[j - 1] + a16 * c; carry[j] = c; }
    }
    __syncthreads();
    float hh = carry[t];
#pragma unroll
    for (int i = 0; i < 16; i++) { hh = a * hh + u[base + i]; h[base + i] = hh; }
}

// ================= k3: fused x_new + stats2 + down-proj/ReLU + up-proj + residual ==========
// 16 rows/block, 512 threads, 134 KB dynamic smem (1 block/SM).
#define K3_SMEM_FLOATS 33504
__global__ void __launch_bounds__(512) k3_kernel(const float* __restrict__ x,
                                                 const float* __restrict__ Wout,
                                                 const float* __restrict__ Wup,
                                                 const float* __restrict__ b_up,
                                                 float* __restrict__ out) {
    extern __shared__ float sm[];
    float* xbuf   = sm;              // 16*2048
    float* f_s    = sm + 32768;      // 16*32
    float* st_s   = sm + 33280;      // 16*2
    float* mu2s   = sm + 33312;      // 16
    float* rs2s   = sm + 33328;      // 16
    float* h_s    = sm + 33344;      // 16*8
    float* mu_s   = sm + 33472;      // 16
    float* rstd_s = sm + 33488;      // 16

    int tid = threadIdx.x, w = tid >> 5, lane = tid & 31;
    int rowBase = blockIdx.x * 16;

    if (tid < 128) {
        int r = tid >> 3, k = tid & 7, row = rowBase + r;
        h_s[tid] = g_hT[(((row >> 12) * 8) + k) * 4096 + (row & 4095)];
    } else if (tid < 144) mu_s[tid - 128] = g_mu[rowBase + tid - 128];
    else if (tid < 160)   rstd_s[tid - 144] = g_rstd[rowBase + tid - 144];
    else if (tid < 192)   st_s[tid - 160] = 0.f;
    __syncthreads();

    int d0 = w * 128 + lane * 4;

    // ---- Phase A: x_new into smem + stats2 partials ----
    {
        float4 GS4 = *(const float4*)(g_GS + d0);
        float4 C4  = *(const float4*)(g_C + d0);
        float4 wo[8];
#pragma unroll
        for (int k = 0; k < 8; k++) wo[k] = *(const float4*)(Wout + k * D + d0);
        float gs[4] = {GS4.x, GS4.y, GS4.z, GS4.w};
        float cc[4] = {C4.x, C4.y, C4.z, C4.w};
#pragma unroll
        for (int r = 0; r < 16; r++) {
            float mu = mu_s[r], rs = rstd_s[r];
            const float4 xv = *(const float4*)(x + (size_t)(rowBase + r) * D + d0);
            float hk[8];
#pragma unroll
            for (int k = 0; k < 8; k++) hk[k] = h_s[r * 8 + k];
            float xe[4] = {xv.x, xv.y, xv.z, xv.w};
            float v[4]; float s1 = 0.f, s2 = 0.f;
#pragma unroll
            for (int e = 0; e < 4; e++) {
                float t = (xe[e] - mu) * rs;
                float a = xe[e] + cc[e] + t * gs[e];
#pragma unroll
                for (int k = 0; k < 8; k++) a = fmaf(hk[k], f4get(wo[k], e), a);
                v[e] = a; s1 += a; s2 = fmaf(a, a, s2);
            }
            *(float4*)(&xbuf[r * D + d0]) = make_float4(v[0], v[1], v[2], v[3]);
            ull ss = pack2(s1, s2);
#pragma unroll
            for (int m = 16; m >= 1; m >>= 1)
                ss = add2(ss, __shfl_xor_sync(0xffffffffu, ss, m));
            if (lane == 0) {
                float a, b; unpack2(ss, a, b);
                atomicAdd(&st_s[2 * r], a); atomicAdd(&st_s[2 * r + 1], b);
            }
        }
    }
    __syncthreads();
    if (tid < 16) {
        float s1 = st_s[2 * tid], s2 = st_s[2 * tid + 1];
        float mu = s1 * (1.f / D);
        float var = s2 * (1.f / D) - mu * mu;
        mu2s[tid] = mu; rs2s[tid] = rsqrtf(var + EPS);
    }
    __syncthreads();

    // ---- Phase B: down-proj (folded LN) + ReLU. Warp owns 4 c's, 8 rows, full depth ----
    {
        int cq = w >> 1, rh = w & 1, c0 = cq * 4;
        ull acc[8][2];
#pragma unroll
        for (int r = 0; r < 8; r++) { acc[r][0] = 0; acc[r][1] = 0; }
#pragma unroll
        for (int j = 0; j < 16; j++) {
            int d = j * 128 + lane * 4;
            float4 wc0 = *(const float4*)(g_WgDownT + (c0 + 0) * D + d);
            float4 wc1 = *(const float4*)(g_WgDownT + (c0 + 1) * D + d);
            float4 wc2 = *(const float4*)(g_WgDownT + (c0 + 2) * D + d);
            float4 wc3 = *(const float4*)(g_WgDownT + (c0 + 3) * D + d);
            ull wA[4], wB[4];
#pragma unroll
            for (int e = 0; e < 4; e++) {
                wA[e] = pack2(f4get(wc0, e), f4get(wc1, e));
                wB[e] = pack2(f4get(wc2, e), f4get(wc3, e));
            }
#pragma unroll
            for (int r = 0; r < 8; r++) {
                const float4 xv = *(const float4*)(&xbuf[(rh * 8 + r) * D + d]);
                float xe[4] = {xv.x, xv.y, xv.z, xv.w};
#pragma unroll
                for (int e = 0; e < 4; e++) {
                    ull x2 = pack2(xe[e], xe[e]);
                    fma2(acc[r][0], wA[e], x2);
                    fma2(acc[r][1], wB[e], x2);
                }
            }
        }
#pragma unroll
        for (int m = 16; m >= 1; m >>= 1)
#pragma unroll
            for (int r = 0; r < 8; r++) {
                acc[r][0] = add2(acc[r][0], __shfl_xor_sync(0xffffffffu, acc[r][0], m));
                acc[r][1] = add2(acc[r][1], __shfl_xor_sync(0xffffffffu, acc[r][1], m));
            }
        if (lane < 8) {
            int r = rh * 8 + lane;
            float mu2 = mu2s[r], rs2 = rs2s[r];
            float dd[4];
            unpack2(acc[lane][0], dd[0], dd[1]);
            unpack2(acc[lane][1], dd[2], dd[3]);
#pragma unroll
            for (int c = 0; c < 4; c++) {
                int ci = c0 + c;
                float pre = rs2 * (dd[c] - mu2 * g_Gd[ci]) + g_Bd[ci];
                f_s[r * 32 + ci] = fmaxf(pre, 0.f);
            }
        }
    }
    __syncthreads();

    // ---- Phase C: up-proj + residual + store ----
    {
        ulonglong2 bup2 = *(const ulonglong2*)(b_up + d0);
#pragma unroll
        for (int rh = 0; rh < 2; rh++) {
            ull acc[8][2];
#pragma unroll
            for (int r = 0; r < 8; r++) {
                ulonglong2 xv = *(const ulonglong2*)(&xbuf[(rh * 8 + r) * D + d0]);
                acc[r][0] = add2(xv.x, bup2.x);
                acc[r][1] = add2(xv.y, bup2.y);
            }
#pragma unroll
            for (int cg = 0; cg < 4; cg++) {
                ull wu[8][2];
#pragma unroll
                for (int c = 0; c < 8; c++) {
                    ulonglong2 wv = *(const ulonglong2*)(Wup + (cg * 8 + c) * D + d0);
                    wu[c][0] = wv.x; wu[c][1] = wv.y;
                }
#pragma unroll
                for (int r = 0; r < 8; r++) {
                    const float4 fA = *(const float4*)(&f_s[(rh * 8 + r) * 32 + cg * 8]);
                    const float4 fB = *(const float4*)(&f_s[(rh * 8 + r) * 32 + cg * 8 + 4]);
                    float fv[8] = {fA.x, fA.y, fA.z, fA.w, fB.x, fB.y, fB.z, fB.w};
#pragma unroll
                    for (int c = 0; c < 8; c++) {
                        ull f2 = pack2(fv[c], fv[c]);
                        fma2(acc[r][0], wu[c][0], f2);
                        fma2(acc[r][1], wu[c][1], f2);
                    }
                }
            }
#pragma unroll
            for (int r = 0; r < 8; r++) {
                float o0, o1, o2, o3;
                unpack2(acc[r][0], o0, o1);
                unpack2(acc[r][1], o2, o3);
                *(float4*)(out + (size_t)(rowBase + rh * 8 + r) * D + d0) =
                    make_float4(o0, o1, o2, o3);
            }
        }
    }
}

// ================= launcher =================
extern "C" void kernel_launch(void* const* d_in, const int* in_sizes, int n_in,
                              void* d_out, int out_size) {
    const float* x      = (const float*)d_in[0];
    const float* gamma  = (const float*)d_in[1];
    const float* beta   = (const float*)d_in[2];
    const float* W_in   = (const float*)d_in[3];
    const float* b_in   = (const float*)d_in[4];
    const float* dlog   = (const float*)d_in[5];
    const float* W_out  = (const float*)d_in[6];
    const float* b_out  = (const float*)d_in[7];
    const float* D_skip = (const float*)d_in[8];
    const float* W_down = (const float*)d_in[9];
    const float* b_down = (const float*)d_in[10];
    const float* W_up   = (const float*)d_in[11];
    const float* b_up   = (const float*)d_in[12];
    float* out = (float*)d_out;

    k0a_kernel<<<256, 256>>>(gamma, beta, W_in, W_down, D_skip, b_out);
    k0b_kernel<<<11, 256>>>(gamma, beta, W_in, b_in, dlog, W_down, b_down);
    k1_kernel<<<1024, 512>>>(x);
    k2_kernel<<<32, 256>>>();

    const int smem = K3_SMEM_FLOATS * 4;
    cudaFuncSetAttribute(k3_kernel, cudaFuncAttributeMaxDynamicSharedMemorySize, smem);
    k3_kernel<<<1024, 512, smem>>>(x, W_out, W_up, b_up, out);
}

// round 10
// speedup vs baseline: 1.4435x; 1.4435x over previous
#include <cuda_runtime.h>

#define D     2048
#define RNK   8
#define RF    32
#define NROWS 16384
#define EPS   1e-5f

typedef unsigned long long ull;

// ---------------- device scratch ----------------
__device__ __align__(16) float g_WgInT[RNK * D];    // gamma[d]*W_in[d][k], [k][d]
__device__ __align__(16) float g_WgDownT[RF * D];   // gamma[d]*W_down[d][c], [c][d]
__device__ __align__(16) float g_GS[D];             // gamma*D_skip
__device__ __align__(16) float g_C[D];              // b_out + beta*D_skip
__device__ __align__(16) float g_Gk[RNK];
__device__ __align__(16) float g_Bk[RNK];
__device__ __align__(16) float g_decay[RNK];
__device__ __align__(16) float g_Gd[RF];
__device__ __align__(16) float g_Bd[RF];
__device__ __align__(16) float g_uT[32 * 4096];
__device__ __align__(16) float g_hT[32 * 4096];
__device__ float g_mu[NROWS], g_rstd[NROWS];

// ---------------- helpers ----------------
__device__ __forceinline__ ull pack2(float lo, float hi) {
    ull r; asm("mov.b64 %0,{%1,%2};" : "=l"(r) : "f"(lo), "f"(hi)); return r;
}
__device__ __forceinline__ void unpack2(ull v, float &lo, float &hi) {
    asm("mov.b64 {%0,%1},%2;" : "=f"(lo), "=f"(hi) : "l"(v));
}
__device__ __forceinline__ void fma2(ull &acc, ull a, ull b) {
    asm("fma.rn.f32x2 %0,%1,%2,%0;" : "+l"(acc) : "l"(a), "l"(b));
}
__device__ __forceinline__ ull add2(ull a, ull b) {
    ull r; asm("add.rn.f32x2 %0,%1,%2;" : "=l"(r) : "l"(a), "l"(b)); return r;
}
__device__ __forceinline__ ull mul2(ull a, ull b) {
    ull r; asm("mul.rn.f32x2 %0,%1,%2;" : "=l"(r) : "l"(a), "l"(b)); return r;
}
__device__ __forceinline__ ull shflx(ull v, int m) {
    return __shfl_xor_sync(0xffffffffu, v, m);
}
__device__ __forceinline__ float wred(float v) {
    v += __shfl_xor_sync(0xffffffffu, v, 16);
    v += __shfl_xor_sync(0xffffffffu, v, 8);
    v += __shfl_xor_sync(0xffffffffu, v, 4);
    v += __shfl_xor_sync(0xffffffffu, v, 2);
    v += __shfl_xor_sync(0xffffffffu, v, 1);
    return v;
}

// ================= k0a: elementwise precompute =================
__global__ void k0a_kernel(const float* __restrict__ gamma, const float* __restrict__ beta,
                           const float* __restrict__ W_in, const float* __restrict__ W_down,
                           const float* __restrict__ D_skip, const float* __restrict__ b_out) {
    int i = blockIdx.x * blockDim.x + threadIdx.x;
    if (i < RF * D) {
        int d = i >> 5, c = i & 31;
        g_WgDownT[c * D + d] = gamma[d] * W_down[i];
    }
    if (i < RNK * D) {
        int d = i >> 3, k = i & 7;
        g_WgInT[k * D + d] = gamma[d] * W_in[i];
    }
    if (i < D) {
        g_GS[i] = gamma[i] * D_skip[i];
        g_C[i]  = b_out[i] + beta[i] * D_skip[i];
    }
}

// ================= k0b: folded-LN constants + decay =================
__global__ void k0b_kernel(const float* __restrict__ gamma, const float* __restrict__ beta,
                           const float* __restrict__ W_in, const float* __restrict__ b_in,
                           const float* __restrict__ dlogit,
                           const float* __restrict__ W_down, const float* __restrict__ b_down) {
    int q = (blockIdx.x * blockDim.x + threadIdx.x) >> 5;
    int lane = threadIdx.x & 31;
    if (q < 8) {
        float a = 0.f;
        for (int d = lane; d < D; d += 32) a += gamma[d] * W_in[d * RNK + q];
        a = wred(a); if (!lane) g_Gk[q] = a;
    } else if (q < 16) {
        int k = q - 8; float a = 0.f;
        for (int d = lane; d < D; d += 32) a += beta[d] * W_in[d * RNK + k];
        a = wred(a); if (!lane) g_Bk[k] = a + b_in[k];
    } else if (q < 48) {
        int c = q - 16; float a = 0.f;
        for (int d = lane; d < D; d += 32) a += gamma[d] * W_down[d * RF + c];
        a = wred(a); if (!lane) g_Gd[c] = a;
    } else if (q < 80) {
        int c = q - 48; float a = 0.f;
        for (int d = lane; d < D; d += 32) a += beta[d] * W_down[d * RF + c];
        a = wred(a); if (!lane) g_Bd[c] = a + b_down[c];
    } else if (q == 80 && lane < RNK) {
        g_decay[lane] = 1.f / (1.f + expf(-dlogit[lane]));
    }
}

// ================= k1: single pass over x -> (mu, rstd) and u =================
// 16 rows/block, 512 threads; warp owns 128-d slice; no atomics (slot writes).
__global__ void __launch_bounds__(512) k1_kernel(const float* __restrict__ x) {
    __shared__ float2 uslot[16][16][5];   // [warp][row][4 udot-pairs + ss]
    __shared__ float musA[16], rstdsA[16];
    int tid = threadIdx.x, w = tid >> 5, lane = tid & 31;
    int rowBase = blockIdx.x * 16;
    int d0 = w * 128 + lane * 4;

    ulonglong2 wk[8];
#pragma unroll
    for (int k = 0; k < 8; k++) wk[k] = *(const ulonglong2*)(g_WgInT + k * D + d0);

#pragma unroll
    for (int r = 0; r < 16; r++) {
        ulonglong2 xv = *(const ulonglong2*)(x + (size_t)(rowBase + r) * D + d0);
        ull acc[8];
#pragma unroll
        for (int k = 0; k < 8; k++) {
            acc[k] = 0ULL;
            fma2(acc[k], xv.x, wk[k].x);
            fma2(acc[k], xv.y, wk[k].y);
        }
        float xa, xb, xc, xd;
        unpack2(xv.x, xa, xb); unpack2(xv.y, xc, xd);
        float s1 = (xa + xb) + (xc + xd);
        float s2 = fmaf(xa, xa, fmaf(xb, xb, fmaf(xc, xc, xd * xd)));
        float uk[8];
#pragma unroll
        for (int k = 0; k < 8; k++) { float lo, hi; unpack2(acc[k], lo, hi); uk[k] = lo + hi; }
        ull pk[4];
#pragma unroll
        for (int p = 0; p < 4; p++) pk[p] = pack2(uk[2 * p], uk[2 * p + 1]);
        ull ss = pack2(s1, s2);
#pragma unroll
        for (int m = 16; m >= 1; m >>= 1) {
            ss = add2(ss, shflx(ss, m));
#pragma unroll
            for (int p = 0; p < 4; p++) pk[p] = add2(pk[p], shflx(pk[p], m));
        }
        if (!lane) {
#pragma unroll
            for (int p = 0; p < 4; p++) {
                float a, b; unpack2(pk[p], a, b);
                uslot[w][r][p] = make_float2(a, b);
            }
            float a, b; unpack2(ss, a, b);
            uslot[w][r][4] = make_float2(a, b);
        }
    }
    __syncthreads();
    if (tid < 16) {
        float s1 = 0.f, s2 = 0.f;
#pragma unroll
        for (int ww = 0; ww < 16; ww++) { float2 v = uslot[ww][tid][4]; s1 += v.x; s2 += v.y; }
        float mu = s1 * (1.f / D);
        float var = s2 * (1.f / D) - mu * mu;
        float rs = rsqrtf(var + EPS);
        musA[tid] = mu; rstdsA[tid] = rs;
        g_mu[rowBase + tid] = mu; g_rstd[rowBase + tid] = rs;
    }
    __syncthreads();
    if (tid < 64) {
        int r = tid >> 2, p = tid & 3;
        float a = 0.f, b = 0.f;
#pragma unroll
        for (int ww = 0; ww < 16; ww++) { float2 v = uslot[ww][r][p]; a += v.x; b += v.y; }
        float mu = musA[r], rs = rstdsA[r];
        int k0 = 2 * p;
        float u0 = rs * (a - mu * g_Gk[k0])     + g_Bk[k0];
        float u1 = rs * (b - mu * g_Gk[k0 + 1]) + g_Bk[k0 + 1];
        int row = rowBase + r;
        int bofs = (row >> 12) * 8, s = row & 4095;
        g_uT[(bofs + k0) * 4096 + s]     = u0;
        g_uT[(bofs + k0 + 1) * 4096 + s] = u1;
    }
}

// ================= k2: 32 scans of length 4096 (parallel block scan) =================
__global__ void k2_kernel() {
    int blk = blockIdx.x;
    const float a = g_decay[blk & 7];
    const float* u = g_uT + blk * 4096;
    float* h = g_hT + blk * 4096;
    int t = threadIdx.x, lane = t & 31, w = t >> 5;   // 256 threads, 8 warps
    int base = t * 16;
    float a2 = a * a, a4 = a2 * a2, a8 = a4 * a4, q16 = a8 * a8;

    float uu[16];
#pragma unroll
    for (int i = 0; i < 16; i++) uu[i] = u[base + i];
    float loc = 0.f;
#pragma unroll
    for (int i = 0; i < 16; i++) loc = fmaf(a, loc, uu[i]);

    // inclusive warp scan with ratio q16
    float qm = q16;
#pragma unroll
    for (int m = 1; m < 32; m <<= 1) {
        float up = __shfl_up_sync(0xffffffffu, loc, m);
        if (lane >= m) loc = fmaf(qm, up, loc);
        qm *= qm;                       // after loop: qm = q16^32
    }
    __shared__ float wtot[8], wcarry[8];
    if (lane == 31) wtot[w] = loc;
    float q512 = qm;
    __syncthreads();
    if (t == 0) {
        float c = 0.f; wcarry[0] = 0.f;
        for (int j = 1; j < 8; j++) { c = fmaf(q512, c, wtot[j - 1]); wcarry[j] = c; }
    }
    __syncthreads();
    // q16^(lane+1) by binary exponentiation
    float pw = 1.f, bb = q16; int e = lane + 1;
    while (e) { if (e & 1) pw *= bb; bb *= bb; e >>= 1; }
    float incl = fmaf(pw, wcarry[w], loc);
    float up1 = __shfl_up_sync(0xffffffffu, incl, 1);
    float excl = lane ? up1 : wcarry[w];

    float hh = excl;
#pragma unroll
    for (int i = 0; i < 16; i++) { hh = fmaf(a, hh, uu[i]); h[base + i] = hh; }
}

// ================= k3: fused x_new + stats2 + down/ReLU + up + residual =================
#define K3_SMEM_FLOATS 33984
__global__ void __launch_bounds__(512, 1) k3_kernel(const float* __restrict__ x,
                                                    const float* __restrict__ Wout,
                                                    const float* __restrict__ Wup,
                                                    const float* __restrict__ b_up,
                                                    float* __restrict__ out) {
    extern __shared__ float sm[];
    float*  xbuf     = sm;                       // 32768
    float*  f_s      = sm + 32768;               // 512
    float2* statSlot = (float2*)(sm + 33280);    // [w*16+r], 512 floats
    float*  mu2s     = sm + 33792;               // 16
    float*  rs2s     = sm + 33808;               // 16
    float*  h_s      = sm + 33824;               // 128
    float*  mu_s     = sm + 33952;               // 16
    float*  rstd_s   = sm + 33968;               // 16

    int tid = threadIdx.x, w = tid >> 5, lane = tid & 31;
    int rowBase = blockIdx.x * 16;

    if (tid < 128) {
        int r = tid >> 3, k = tid & 7, row = rowBase + r;
        h_s[tid] = g_hT[((row >> 12) * 8 + k) * 4096 + (row & 4095)];
    } else if (tid < 144) mu_s[tid - 128] = g_mu[rowBase + tid - 128];
    else if (tid < 160)   rstd_s[tid - 144] = g_rstd[rowBase + tid - 144];
    __syncthreads();

    int d0 = w * 128 + lane * 4;

    // ---- Phase A: x_new -> smem, per-row stats2 partials via slot writes ----
    {
        ulonglong2 gs2 = *(const ulonglong2*)(g_GS + d0);
        ulonglong2 cc2 = *(const ulonglong2*)(g_C + d0);
        ulonglong2 wo2[8];
#pragma unroll
        for (int k = 0; k < 8; k++) wo2[k] = *(const ulonglong2*)(Wout + k * D + d0);
#pragma unroll
        for (int r = 0; r < 16; r++) {
            float mu = mu_s[r], rs = rstd_s[r];
            ull h2[8];
#pragma unroll
            for (int k = 0; k < 8; k++) { float hv = h_s[r * 8 + k]; h2[k] = pack2(hv, hv); }
            ulonglong2 xv = *(const ulonglong2*)(x + (size_t)(rowBase + r) * D + d0);
            ull negmu = pack2(-mu, -mu), rsp = pack2(rs, rs);
            ull a0, a1;
            {
                ull rsgs = mul2(gs2.x, rsp);
                ull tt = add2(xv.x, negmu);
                a0 = add2(xv.x, cc2.x);
                fma2(a0, tt, rsgs);
#pragma unroll
                for (int k = 0; k < 8; k++) fma2(a0, h2[k], wo2[k].x);
            }
            {
                ull rsgs = mul2(gs2.y, rsp);
                ull tt = add2(xv.y, negmu);
                a1 = add2(xv.y, cc2.y);
                fma2(a1, tt, rsgs);
#pragma unroll
                for (int k = 0; k < 8; k++) fma2(a1, h2[k], wo2[k].y);
            }
            ull s1p = add2(a0, a1);
            ull s2p = 0ULL; fma2(s2p, a0, a0); fma2(s2p, a1, a1);
            float sa, sb; unpack2(s1p, sa, sb); float s1 = sa + sb;
            unpack2(s2p, sa, sb); float s2 = sa + sb;
            ulonglong2 ov; ov.x = a0; ov.y = a1;
            *(ulonglong2*)(&xbuf[r * D + d0]) = ov;
            ull ss = pack2(s1, s2);
#pragma unroll
            for (int m = 16; m >= 1; m >>= 1) ss = add2(ss, shflx(ss, m));
            if (!lane) { float p1, p2; unpack2(ss, p1, p2); statSlot[w * 16 + r] = make_float2(p1, p2); }
        }
    }
    __syncthreads();
    if (tid < 16) {
        float s1 = 0.f, s2 = 0.f;
#pragma unroll
        for (int ww = 0; ww < 16; ww++) { float2 v = statSlot[ww * 16 + tid]; s1 += v.x; s2 += v.y; }
        float mu = s1 * (1.f / D);
        float var = s2 * (1.f / D) - mu * mu;
        mu2s[tid] = mu; rs2s[tid] = rsqrtf(var + EPS);
    }
    __syncthreads();

    // ---- Phase B: down-proj + folded LN + ReLU (warp = (c-quad, row-half), full depth) ----
    {
        int cq = w >> 1, rh = w & 1, c0 = cq * 4;
        ull acc[8][4];
#pragma unroll
        for (int r = 0; r < 8; r++)
#pragma unroll
            for (int c = 0; c < 4; c++) acc[r][c] = 0ULL;
#pragma unroll
        for (int j = 0; j < 16; j++) {
            int d = j * 128 + lane * 4;
            ulonglong2 wv[4];
#pragma unroll
            for (int c = 0; c < 4; c++) wv[c] = *(const ulonglong2*)(g_WgDownT + (c0 + c) * D + d);
#pragma unroll
            for (int r = 0; r < 8; r++) {
                ulonglong2 xv = *(const ulonglong2*)(&xbuf[(rh * 8 + r) * D + d]);
#pragma unroll
                for (int c = 0; c < 4; c++) {
                    fma2(acc[r][c], xv.x, wv[c].x);
                    fma2(acc[r][c], xv.y, wv[c].y);
                }
            }
        }
        ull pk[8][2];
#pragma unroll
        for (int r = 0; r < 8; r++) {
            float dc[4];
#pragma unroll
            for (int c = 0; c < 4; c++) { float lo, hi; unpack2(acc[r][c], lo, hi); dc[c] = lo + hi; }
            pk[r][0] = pack2(dc[0], dc[1]);
            pk[r][1] = pack2(dc[2], dc[3]);
        }
#pragma unroll
        for (int m = 16; m >= 1; m >>= 1)
#pragma unroll
            for (int r = 0; r < 8; r++) {
                pk[r][0] = add2(pk[r][0], shflx(pk[r][0], m));
                pk[r][1] = add2(pk[r][1], shflx(pk[r][1], m));
            }
        if (lane < 8) {
            int row = rh * 8 + lane;
            float mu2 = mu2s[row], rs2 = rs2s[row];
            float v0, v1, v2, v3;
            unpack2(pk[lane][0], v0, v1);
            unpack2(pk[lane][1], v2, v3);
            float4 Gd4 = *(const float4*)(g_Gd + c0);
            float4 Bd4 = *(const float4*)(g_Bd + c0);
            f_s[row * 32 + c0 + 0] = fmaxf(fmaf(rs2, fmaf(-mu2, Gd4.x, v0), Bd4.x), 0.f);
            f_s[row * 32 + c0 + 1] = fmaxf(fmaf(rs2, fmaf(-mu2, Gd4.y, v1), Bd4.y), 0.f);
            f_s[row * 32 + c0 + 2] = fmaxf(fmaf(rs2, fmaf(-mu2, Gd4.z, v2), Bd4.z), 0.f);
            f_s[row * 32 + c0 + 3] = fmaxf(fmaf(rs2, fmaf(-mu2, Gd4.w, v3), Bd4.w), 0.f);
        }
    }
    __syncthreads();

    // ---- Phase C: up-proj + residual + store (weights loaded once per c-group) ----
    {
        ulonglong2 bup = *(const ulonglong2*)(b_up + d0);
        ull acc[16][2];
#pragma unroll
        for (int rr = 0; rr < 16; rr++) {
            ulonglong2 xv = *(const ulonglong2*)(&xbuf[rr * D + d0]);
            acc[rr][0] = add2(xv.x, bup.x);
            acc[rr][1] = add2(xv.y, bup.y);
        }
#pragma unroll
        for (int g = 0; g < 8; g++) {
            ulonglong2 wv[4];
#pragma unroll
            for (int c = 0; c < 4; c++) wv[c] = *(const ulonglong2*)(Wup + (g * 4 + c) * D + d0);
#pragma unroll
            for (int rr = 0; rr < 16; rr++) {
                float4 f4 = *(const float4*)(&f_s[rr * 32 + g * 4]);
                ull f0 = pack2(f4.x, f4.x), f1 = pack2(f4.y, f4.y);
                ull f2v = pack2(f4.z, f4.z), f3 = pack2(f4.w, f4.w);
                fma2(acc[rr][0], f0, wv[0].x); fma2(acc[rr][1], f0, wv[0].y);
                fma2(acc[rr][0], f1, wv[1].x); fma2(acc[rr][1], f1, wv[1].y);
                fma2(acc[rr][0], f2v, wv[2].x); fma2(acc[rr][1], f2v, wv[2].y);
                fma2(acc[rr][0], f3, wv[3].x); fma2(acc[rr][1], f3, wv[3].y);
            }
        }
#pragma unroll
        for (int rr = 0; rr < 16; rr++) {
            ulonglong2 ov; ov.x = acc[rr][0]; ov.y = acc[rr][1];
            *(ulonglong2*)(out + (size_t)(rowBase + rr) * D + d0) = ov;
        }
    }
}

// ================= launcher =================
extern "C" void kernel_launch(void* const* d_in, const int* in_sizes, int n_in,
                              void* d_out, int out_size) {
    const float* x      = (const float*)d_in[0];
    const float* gamma  = (const float*)d_in[1];
    const float* beta   = (const float*)d_in[2];
    const float* W_in   = (const float*)d_in[3];
    const float* b_in   = (const float*)d_in[4];
    const float* dlog   = (const float*)d_in[5];
    const float* W_out  = (const float*)d_in[6];
    const float* b_out  = (const float*)d_in[7];
    const float* D_skip = (const float*)d_in[8];
    const float* W_down = (const float*)d_in[9];
    const float* b_down = (const float*)d_in[10];
    const float* W_up   = (const float*)d_in[11];
    const float* b_up   = (const float*)d_in[12];
    float* out = (float*)d_out;

    k0a_kernel<<<256, 256>>>(gamma, beta, W_in, W_down, D_skip, b_out);
    k0b_kernel<<<11, 256>>>(gamma, beta, W_in, b_in, dlog, W_down, b_down);
    k1_kernel<<<1024, 512>>>(x);
    k2_kernel<<<32, 256>>>();

    const int smem = K3_SMEM_FLOATS * 4;
    cudaFuncSetAttribute(k3_kernel, cudaFuncAttributeMaxDynamicSharedMemorySize, smem);
    k3_kernel<<<1024, 512, smem>>>(x, W_out, W_up, b_up, out);
}